// round 1
// baseline (speedup 1.0000x reference)
#include <cuda_runtime.h>
#include <cuda_bf16.h>
#include <math.h>
#include <stdint.h>

// Problem constants
#define NB   8
#define C    512
#define H    50
#define W    76
#define HW   3800          // H*W
#define NA   34200         // HW*9
#define SORTN 65536
#define PRE  6000
#define WORDS 94           // ceil(6000/64)
#define POST 300

// Output layout (float32, concatenated in return order)
#define LOC_OFF   0
#define SCORE_OFF (NB*NA*4)                 // 1094400
#define ROI_OFF   (SCORE_OFF + NB*NA*2)     // 1641600
#define ANCH_OFF  (ROI_OFF + NB*POST*4)     // 1651200

// Scratch (static device globals — no runtime allocation)
__device__ float              g_feat[(size_t)NB*HW*C];       // NHWC, ~62MB
__device__ float              g_boxes[(size_t)NB*NA*4];
__device__ unsigned long long g_keys[(size_t)NB*SORTN];
__device__ float              g_sbox[(size_t)NB*PRE*4];
__device__ float              g_sarea[(size_t)NB*PRE];
__device__ unsigned char      g_sfin[(size_t)NB*PRE];
__device__ unsigned long long g_mask[(size_t)NB*PRE*WORDS];  // ~36MB

// ---------------------------------------------------------------------------
// conv1: 3x3 SAME 512->512 + bias + ReLU.  Tile: 64 oc x 40 px (one row),
// ic chunks of 8. Block 128 threads, each computes 4 oc x 5 px.
// ---------------------------------------------------------------------------
__global__ __launch_bounds__(128) void k_conv1(const float* __restrict__ x,
                                               const float* __restrict__ wconv,
                                               const float* __restrict__ bias) {
    const int xt  = blockIdx.x;          // 0..1
    const int y   = blockIdx.y >> 3;     // 0..49
    const int oct = blockIdx.y & 7;      // 0..7
    const int n   = blockIdx.z;
    const int x0  = xt * 40;
    const int oc0 = oct * 64;

    __shared__ float xs[8][3][42];       // [ic][dy][col], col0 <-> x0-1
    __shared__ float ws[8][9][64];       // [ic][tap][oc]

    const int t  = threadIdx.x;
    const int tx = t & 7;                // px group (5 px each)
    const int ty = t >> 3;               // oc group (4 oc each)

    float acc[4][5];
#pragma unroll
    for (int k = 0; k < 4; ++k)
#pragma unroll
        for (int p = 0; p < 5; ++p) acc[k][p] = 0.f;

    const float* xn = x + (size_t)n * C * HW;

    for (int kc = 0; kc < C / 8; ++kc) {
        const int ic0 = kc * 8;
        // load weights: 64 oc x 8 ic x 9 taps
        const float* wbase = wconv + ((size_t)oc0 * C + ic0) * 9;
        for (int i = t; i < 64 * 8 * 9; i += 128) {
            int ocr = i / 72, r = i % 72, ic = r / 9, tap = r % 9;
            ws[ic][tap][ocr] = wbase[(size_t)ocr * C * 9 + ic * 9 + tap];
        }
        // load input tile: 8 ic x 3 rows x 42 cols (zero-padded)
        for (int i = t; i < 8 * 3 * 42; i += 128) {
            int ic = i / 126, r = i % 126, dy = r / 42, cx = r % 42;
            int yy = y + dy - 1, xx = x0 + cx - 1;
            float v = 0.f;
            if ((unsigned)yy < (unsigned)H && (unsigned)xx < (unsigned)W)
                v = xn[(size_t)(ic0 + ic) * HW + yy * W + xx];
            xs[ic][dy][cx] = v;
        }
        __syncthreads();
#pragma unroll
        for (int ic = 0; ic < 8; ++ic) {
#pragma unroll
            for (int dy = 0; dy < 3; ++dy) {
#pragma unroll
                for (int dx = 0; dx < 3; ++dx) {
                    float wv0 = ws[ic][dy * 3 + dx][ty * 4 + 0];
                    float wv1 = ws[ic][dy * 3 + dx][ty * 4 + 1];
                    float wv2 = ws[ic][dy * 3 + dx][ty * 4 + 2];
                    float wv3 = ws[ic][dy * 3 + dx][ty * 4 + 3];
                    float xv[5];
#pragma unroll
                    for (int p = 0; p < 5; ++p) xv[p] = xs[ic][dy][tx * 5 + p + dx];
#pragma unroll
                    for (int p = 0; p < 5; ++p) {
                        acc[0][p] += wv0 * xv[p];
                        acc[1][p] += wv1 * xv[p];
                        acc[2][p] += wv2 * xv[p];
                        acc[3][p] += wv3 * xv[p];
                    }
                }
            }
        }
        __syncthreads();
    }
    // epilogue: bias + relu, write NHWC feat
    float* fb = g_feat + ((size_t)n * HW + (size_t)y * W) * C;
#pragma unroll
    for (int k = 0; k < 4; ++k) {
        float bb = bias[oc0 + ty * 4 + k];
#pragma unroll
        for (int p = 0; p < 5; ++p) {
            int px = x0 + tx * 5 + p;
            if (px < W)
                fb[(size_t)px * C + oc0 + ty * 4 + k] = fmaxf(acc[k][p] + bb, 0.f);
        }
    }
}

// ---------------------------------------------------------------------------
// heads: 1x1 convs (18 score + 36 loc = 54 outs) over 512 channels.
// Block: 256 threads, 16 pixels. thread: o = t&63 (54 used), ty = t>>6 (4 px).
// ---------------------------------------------------------------------------
__global__ __launch_bounds__(256) void k_heads(const float* __restrict__ sw,
                                               const float* __restrict__ sb,
                                               const float* __restrict__ lw,
                                               const float* __restrict__ lb,
                                               float* __restrict__ out) {
    const int n  = blockIdx.y;
    const int p0 = blockIdx.x * 16;
    __shared__ float fs[16][68];
    __shared__ float wsm[54][65];
    const int t  = threadIdx.x;
    const int o  = t & 63;
    const int ty = t >> 6;
    float acc[4] = {0.f, 0.f, 0.f, 0.f};

    for (int c0 = 0; c0 < C; c0 += 64) {
        for (int i = t; i < 16 * 64; i += 256) {
            int px = i >> 6, ic = i & 63;
            int p = p0 + px;
            fs[px][ic] = (p < HW) ? g_feat[((size_t)n * HW + p) * C + c0 + ic] : 0.f;
        }
        for (int i = t; i < 54 * 64; i += 256) {
            int oo = i >> 6, ic = i & 63;
            wsm[oo][ic] = (oo < 18) ? sw[oo * C + c0 + ic] : lw[(oo - 18) * C + c0 + ic];
        }
        __syncthreads();
        if (o < 54) {
#pragma unroll 16
            for (int ic = 0; ic < 64; ++ic) {
                float wv = wsm[o][ic];
#pragma unroll
                for (int pi = 0; pi < 4; ++pi) acc[pi] += wv * fs[ty * 4 + pi][ic];
            }
        }
        __syncthreads();
    }
    if (o < 54) {
        float bb = (o < 18) ? sb[o] : lb[o - 18];
#pragma unroll
        for (int pi = 0; pi < 4; ++pi) {
            int p = p0 + ty * 4 + pi;
            if (p < HW) {
                float v = acc[pi] + bb;
                if (o < 18) {
                    int a = o >> 1, cls = o & 1;
                    out[SCORE_OFF + ((size_t)n * NA + (size_t)p * 9 + a) * 2 + cls] = v;
                } else {
                    int c = o - 18, a = c >> 2, coord = c & 3;
                    out[LOC_OFF + ((size_t)n * NA + (size_t)p * 9 + a) * 4 + coord] = v;
                }
            }
        }
    }
}

// ---------------------------------------------------------------------------
// decode: anchors + loc2bbox + clip + valid + softmax-fg -> sortable keys
// ---------------------------------------------------------------------------
__global__ void k_decode(const float* __restrict__ out,
                         const int* __restrict__ ih, const int* __restrict__ iw,
                         float* __restrict__ outw) {
    int id = blockIdx.x * blockDim.x + threadIdx.x;
    if (id >= NB * SORTN) return;
    int n = id >> 16, site = id & (SORTN - 1);
    if (site >= NA) { g_keys[(size_t)n * SORTN + site] = 0ull; return; }

    int p = site / 9, a = site % 9;
    int yy = p / W, xx = p % W;
    int ri = a / 3, sj = a % 3;
    const float ratios[3] = {0.5f, 1.0f, 2.0f};
    const float scales[3] = {8.0f, 16.0f, 32.0f};
    float r = ratios[ri], s = scales[sj];
    float hh = 16.0f * s * sqrtf(r);
    float ww = 16.0f * s * sqrtf(1.0f / r);
    float sx = (float)xx * 16.0f, sy = (float)yy * 16.0f;
    float a0 = sx + (8.0f - ww * 0.5f);
    float a1 = sy + (8.0f - hh * 0.5f);
    float a2 = sx + (8.0f + ww * 0.5f);
    float a3 = sy + (8.0f + hh * 0.5f);
    if (n == 0) {
        float* ao = outw + ANCH_OFF + (size_t)site * 4;
        ao[0] = a0; ao[1] = a1; ao[2] = a2; ao[3] = a3;
    }
    const float* lp = out + LOC_OFF + ((size_t)n * NA + site) * 4;
    float l0 = lp[0], l1 = lp[1], l2 = lp[2], l3 = lp[3];
    float aw = a2 - a0, ah = a3 - a1;
    float ax = a0 + 0.5f * aw, ay = a1 + 0.5f * ah;
    float cx = l0 * aw + ax, cy = l1 * ah + ay;
    float bw = (float)exp((double)l2) * aw;
    float bh = (float)exp((double)l3) * ah;
    float Wf = (float)(*iw), Hf = (float)(*ih);
    float x1 = fminf(fmaxf(cx - 0.5f * bw, 0.f), Wf);
    float y1 = fminf(fmaxf(cy - 0.5f * bh, 0.f), Hf);
    float x2 = fminf(fmaxf(cx + 0.5f * bw, 0.f), Wf);
    float y2 = fminf(fmaxf(cy + 0.5f * bh, 0.f), Hf);
    float* bo = g_boxes + ((size_t)n * NA + site) * 4;
    bo[0] = x1; bo[1] = y1; bo[2] = x2; bo[3] = y2;
    bool valid = ((x2 - x1) >= 16.0f) && ((y2 - y1) >= 16.0f);
    const float* sp = out + SCORE_OFF + ((size_t)n * NA + site) * 2;
    float s0 = sp[0], s1 = sp[1];
    float m = fmaxf(s0, s1);
    float e0 = (float)exp((double)(s0 - m));
    float e1 = (float)exp((double)(s1 - m));
    float fg = e1 / (e0 + e1);
    float sc = valid ? fg : -INFINITY;
    unsigned ub = __float_as_uint(sc);
    unsigned u  = (ub & 0x80000000u) ? ~ub : (ub | 0x80000000u);
    g_keys[(size_t)n * SORTN + site] =
        ((unsigned long long)u << 32) | (unsigned)(~(unsigned)site);
}

// ---------------------------------------------------------------------------
// Bitonic sort, descending, 65536 keys per image.
// ---------------------------------------------------------------------------
__global__ __launch_bounds__(1024) void k_sort_local() {
    __shared__ unsigned long long sm[2048];
    const int n = blockIdx.y, ch = blockIdx.x;
    unsigned long long* base = g_keys + (size_t)n * SORTN + (size_t)ch * 2048;
    const int t = threadIdx.x;
    sm[t] = base[t]; sm[t + 1024] = base[t + 1024];
    __syncthreads();
    const int gbase = ch * 2048;
    for (int k = 2; k <= 2048; k <<= 1) {
        for (int j = k >> 1; j > 0; j >>= 1) {
            int i = ((t & ~(j - 1)) << 1) | (t & (j - 1));
            int p = i | j;
            bool descBlk = (((gbase + i) & k) == 0);
            unsigned long long A = sm[i], B = sm[p];
            bool sw = descBlk ? (A < B) : (A > B);
            if (sw) { sm[i] = B; sm[p] = A; }
            __syncthreads();
        }
    }
    base[t] = sm[t]; base[t + 1024] = sm[t + 1024];
}

__global__ void k_sort_global(int k, int j) {
    int t = blockIdx.x * blockDim.x + threadIdx.x;   // 0..32767
    int n = blockIdx.y;
    int i = ((t & ~(j - 1)) << 1) | (t & (j - 1));
    int p = i | j;
    unsigned long long* base = g_keys + (size_t)n * SORTN;
    unsigned long long A = base[i], B = base[p];
    bool descBlk = ((i & k) == 0);
    bool sw = descBlk ? (A < B) : (A > B);
    if (sw) { base[i] = B; base[p] = A; }
}

__global__ __launch_bounds__(1024) void k_sort_localmerge(int k) {
    __shared__ unsigned long long sm[2048];
    const int n = blockIdx.y, ch = blockIdx.x;
    unsigned long long* base = g_keys + (size_t)n * SORTN + (size_t)ch * 2048;
    const int t = threadIdx.x;
    sm[t] = base[t]; sm[t + 1024] = base[t + 1024];
    __syncthreads();
    const bool descBlk = (((ch * 2048) & k) == 0);
    for (int j = 1024; j > 0; j >>= 1) {
        int i = ((t & ~(j - 1)) << 1) | (t & (j - 1));
        int p = i | j;
        unsigned long long A = sm[i], B = sm[p];
        bool sw = descBlk ? (A < B) : (A > B);
        if (sw) { sm[i] = B; sm[p] = A; }
        __syncthreads();
    }
    base[t] = sm[t]; base[t + 1024] = sm[t + 1024];
}

// ---------------------------------------------------------------------------
// gather top-6000 boxes/areas/finite flags in sorted order
// ---------------------------------------------------------------------------
__global__ void k_gather() {
    int id = blockIdx.x * blockDim.x + threadIdx.x;
    if (id >= NB * PRE) return;
    int n = id / PRE, r = id % PRE;
    unsigned long long key = g_keys[(size_t)n * SORTN + r];
    unsigned site = ~(unsigned)key;
    bool fin = ((unsigned)(key >> 32)) > 0x007FFFFFu;
    float b0 = 0.f, b1 = 0.f, b2 = 0.f, b3 = 0.f;
    if (site < NA) {
        const float* bx = g_boxes + ((size_t)n * NA + site) * 4;
        b0 = bx[0]; b1 = bx[1]; b2 = bx[2]; b3 = bx[3];
    }
    float* sb = g_sbox + ((size_t)n * PRE + r) * 4;
    sb[0] = b0; sb[1] = b1; sb[2] = b2; sb[3] = b3;
    g_sarea[(size_t)n * PRE + r] = (b2 - b0) * (b3 - b1);
    g_sfin[(size_t)n * PRE + r]  = fin ? 1 : 0;
}

// ---------------------------------------------------------------------------
// mask: bit (i, j) set iff j>i and IoU(i,j) > 0.7
// ---------------------------------------------------------------------------
__global__ void k_mask() {
    int id = blockIdx.x * blockDim.x + threadIdx.x;
    int n = blockIdx.y;
    if (id >= PRE * WORDS) return;
    int i = id / WORDS, w_ = id % WORDS;
    unsigned long long bits = 0ull;
    if (w_ * 64 + 63 > i) {
        const float* bi = g_sbox + ((size_t)n * PRE + i) * 4;
        float ix1 = bi[0], iy1 = bi[1], ix2 = bi[2], iy2 = bi[3];
        float ia = g_sarea[(size_t)n * PRE + i];
        int jmax = min(64, PRE - w_ * 64);
        for (int jj = 0; jj < jmax; ++jj) {
            int j = w_ * 64 + jj;
            if (j <= i) continue;
            const float* bj = g_sbox + ((size_t)n * PRE + j) * 4;
            float xx1 = fmaxf(ix1, bj[0]);
            float yy1 = fmaxf(iy1, bj[1]);
            float xx2 = fminf(ix2, bj[2]);
            float yy2 = fminf(iy2, bj[3]);
            float iw_ = fmaxf(xx2 - xx1, 0.f);
            float ihh = fmaxf(yy2 - yy1, 0.f);
            float inter = iw_ * ihh;
            float denom = ((ia + g_sarea[(size_t)n * PRE + j]) - inter) + 1e-9f;
            float iou = inter / denom;
            if (iou > 0.7f) bits |= (1ull << jj);
        }
    }
    g_mask[((size_t)n * PRE + i) * WORDS + w_] = bits;
}

// ---------------------------------------------------------------------------
// scan: greedy NMS (word-sequential), then emit first 300 kept boxes
// ---------------------------------------------------------------------------
__global__ __launch_bounds__(128) void k_scan(float* __restrict__ out) {
    const int n = blockIdx.x;
    __shared__ unsigned long long keep[WORDS];
    __shared__ unsigned long long mrow[64];
    __shared__ unsigned long long remv;
    const int t = threadIdx.x;
    if (t < WORDS) {
        unsigned long long wbits = 0ull;
        for (int b = 0; b < 64; ++b) {
            int i = t * 64 + b;
            if (i < PRE && g_sfin[(size_t)n * PRE + i]) wbits |= (1ull << b);
        }
        keep[t] = wbits;
    }
    __syncthreads();
    for (int w_ = 0; w_ < WORDS; ++w_) {
        if (t == 0) remv = 0ull;
        if (t < 64) {
            int i = w_ * 64 + t;
            mrow[t] = (i < PRE) ? g_mask[((size_t)n * PRE + i) * WORDS + w_] : 0ull;
        }
        __syncthreads();
        unsigned long long loc = 0ull;
        for (int i = t; i < w_ * 64; i += 128)
            if ((keep[i >> 6] >> (i & 63)) & 1ull)
                loc |= g_mask[((size_t)n * PRE + i) * WORDS + w_];
        if (loc) atomicOr(&remv, loc);
        __syncthreads();
        if (t == 0) {
            unsigned long long kw = keep[w_] & ~remv;
            unsigned long long res = 0ull;
            for (int b = 0; b < 64; ++b) {
                if ((kw >> b) & 1ull) { res |= (1ull << b); kw &= ~mrow[b]; }
            }
            keep[w_] = res;
        }
        __syncthreads();
    }
    if (t == 0) {
        int r = 0;
        for (int i = 0; i < PRE && r < POST; ++i) {
            if ((keep[i >> 6] >> (i & 63)) & 1ull) {
                float* o = out + ROI_OFF + ((size_t)n * POST + r) * 4;
                const float* bx = g_sbox + ((size_t)n * PRE + i) * 4;
                o[0] = bx[0]; o[1] = bx[1]; o[2] = bx[2]; o[3] = bx[3];
                ++r;
            }
        }
        for (; r < POST; ++r) {
            float* o = out + ROI_OFF + ((size_t)n * POST + r) * 4;
            o[0] = 0.f; o[1] = 0.f; o[2] = 0.f; o[3] = 0.f;
        }
    }
}

// ---------------------------------------------------------------------------
extern "C" void kernel_launch(void* const* d_in, const int* in_sizes, int n_in,
                              void* d_out, int out_size) {
    const float* x       = (const float*)d_in[0];
    const float* conv1_w = (const float*)d_in[1];
    const float* conv1_b = (const float*)d_in[2];
    const float* score_w = (const float*)d_in[3];
    const float* score_b = (const float*)d_in[4];
    const float* loc_w   = (const float*)d_in[5];
    const float* loc_b   = (const float*)d_in[6];
    const int*   img_h   = (const int*)d_in[7];
    const int*   img_w   = (const int*)d_in[8];
    float* out = (float*)d_out;

    k_conv1<<<dim3(2, 400, NB), 128>>>(x, conv1_w, conv1_b);
    k_heads<<<dim3((HW + 15) / 16, NB), 256>>>(score_w, score_b, loc_w, loc_b, out);
    k_decode<<<(NB * SORTN + 255) / 256, 256>>>(out, img_h, img_w, out);

    k_sort_local<<<dim3(SORTN / 2048, NB), 1024>>>();
    for (int k = 4096; k <= SORTN; k <<= 1) {
        for (int j = k >> 1; j >= 2048; j >>= 1)
            k_sort_global<<<dim3(SORTN / 2 / 256, NB), 256>>>(k, j);
        k_sort_localmerge<<<dim3(SORTN / 2048, NB), 1024>>>(k);
    }

    k_gather<<<(NB * PRE + 255) / 256, 256>>>();
    k_mask<<<dim3((PRE * WORDS + 255) / 256, NB), 256>>>();
    k_scan<<<NB, 128>>>(out);
}

// round 2
// speedup vs baseline: 1.9918x; 1.9918x over previous
#include <cuda_runtime.h>
#include <cuda_bf16.h>
#include <math.h>
#include <stdint.h>

// Problem constants
#define NB   8
#define C    512
#define H    50
#define W    76
#define HW   3800          // H*W
#define NA   34200         // HW*9
#define SORTN 65536
#define PRE  6000
#define WORDS 94           // ceil(6000/64)
#define POST 300

// Output layout (float32, concatenated in return order)
#define LOC_OFF   0
#define SCORE_OFF (NB*NA*4)                 // 1094400
#define ROI_OFF   (SCORE_OFF + NB*NA*2)     // 1641600
#define ANCH_OFF  (ROI_OFF + NB*POST*4)     // 1651200

// Scratch (static device globals — no runtime allocation)
__device__ float              g_feat[(size_t)NB*HW*C];       // NHWC, ~62MB
__device__ float              g_wT[(size_t)C*9*C];           // [ic*9+tap][oc]
__device__ float              g_boxes[(size_t)NB*NA*4];
__device__ unsigned long long g_keys[(size_t)NB*SORTN];
__device__ float              g_sbox[(size_t)NB*PRE*4];
__device__ float              g_sarea[(size_t)NB*PRE];
__device__ unsigned char      g_sfin[(size_t)NB*PRE];
__device__ unsigned long long g_mask[(size_t)NB*PRE*WORDS];  // ~36MB

// ---------------------------------------------------------------------------
// weight transpose: OIHW(3x3) -> [ic*9+tap][oc]
// ---------------------------------------------------------------------------
__global__ void k_wt(const float* __restrict__ w) {
    int i = blockIdx.x * 256 + threadIdx.x;
    if (i >= C * C * 9) return;
    int oc = i & 511;          // C=512
    int row = i >> 9;          // ic*9+tap
    g_wT[i] = w[(size_t)oc * (C * 9) + row];
}

// ---------------------------------------------------------------------------
// conv1: 3x3 SAME 512->512 + bias + ReLU, f32x2 packed FMA.
// Block tile: 64 oc x 2 rows x 76 px. 128 threads.
// Thread: 8 oc (4 packed pairs) x 10 px in one row.
// ic chunks of 4.
// ---------------------------------------------------------------------------
#define ICC 4
__global__ __launch_bounds__(128) void k_conv1(const float* __restrict__ x,
                                               const float* __restrict__ bias) {
    const int ocb = blockIdx.x;       // 0..7
    const int yt  = blockIdx.y;       // 0..24
    const int n   = blockIdx.z;
    const int y0  = yt * 2;
    const int oc0 = ocb * 64;

    __shared__ float xs[ICC][4][80];   // rows y0-1..y0+2, col idx c <-> gx = c-1
    __shared__ float ws[ICC * 9][64];  // [ic*9+tap][oc]

    const int t    = threadIdx.x;
    const int ocg  = t & 7;            // 8 oc each
    const int trow = (t >> 3) & 1;     // row within tile
    const int colg = t >> 4;           // 0..7, 10 px each
    const int c0   = colg * 10;

    unsigned long long acc[4][10];
#pragma unroll
    for (int op = 0; op < 4; ++op)
#pragma unroll
        for (int p = 0; p < 10; ++p) acc[op][p] = 0ull;

    const float* xn = x + (size_t)n * C * HW;

    for (int kc = 0; kc < C / ICC; ++kc) {
        const int ic0 = kc * ICC;
        // weights: ICC*9 rows x 64 oc, coalesced from g_wT
        for (int i = t; i < ICC * 9 * 64; i += 128) {
            int row = i >> 6;   // 0..35
            int oc  = i & 63;
            (&ws[0][0])[i] = g_wT[(size_t)(ic0 * 9 + row) * C + oc0 + oc];
        }
        // input tile: ICC ic x 4 rows x 78 cols (padded stride 80)
        for (int i = t; i < ICC * 4 * 80; i += 128) {
            int ic = i / 320;
            int r  = (i / 80) & 3;
            int c  = i % 80;
            int yy = y0 - 1 + r;
            int gx = c - 1;
            float v = 0.f;
            if ((unsigned)yy < (unsigned)H && (unsigned)gx < (unsigned)W)
                v = xn[(size_t)(ic0 + ic) * HW + yy * W + gx];
            xs[ic][r][c] = v;
        }
        __syncthreads();
#pragma unroll
        for (int ic = 0; ic < ICC; ++ic) {
#pragma unroll
            for (int ky = 0; ky < 3; ++ky) {
                unsigned long long xd[12];
#pragma unroll
                for (int j = 0; j < 12; ++j) {
                    unsigned xv = __float_as_uint(xs[ic][trow + ky][c0 + j]);
                    asm("mov.b64 %0, {%1, %1};" : "=l"(xd[j]) : "r"(xv));
                }
#pragma unroll
                for (int kx = 0; kx < 3; ++kx) {
#pragma unroll
                    for (int op = 0; op < 4; ++op) {
                        unsigned long long w2 =
                            *(const unsigned long long*)&ws[ic * 9 + ky * 3 + kx][ocg * 8 + op * 2];
#pragma unroll
                        for (int p = 0; p < 10; ++p)
                            asm("fma.rn.f32x2 %0, %1, %2, %0;"
                                : "+l"(acc[op][p]) : "l"(xd[p + kx]), "l"(w2));
                    }
                }
            }
        }
        __syncthreads();
    }

    // epilogue: bias + relu, write NHWC feat as float2 (oc pairs contiguous)
    const int y = y0 + trow;
    float* fb = g_feat + ((size_t)n * HW + (size_t)y * W) * C;
#pragma unroll
    for (int op = 0; op < 4; ++op) {
        int oc = oc0 + ocg * 8 + op * 2;
        float b0 = bias[oc], b1 = bias[oc + 1];
#pragma unroll
        for (int p = 0; p < 10; ++p) {
            int px = c0 + p;
            if (px < W) {
                unsigned lo, hi;
                asm("mov.b64 {%0, %1}, %2;" : "=r"(lo), "=r"(hi) : "l"(acc[op][p]));
                float2 v;
                v.x = fmaxf(__uint_as_float(lo) + b0, 0.f);
                v.y = fmaxf(__uint_as_float(hi) + b1, 0.f);
                *(float2*)&fb[(size_t)px * C + oc] = v;
            }
        }
    }
}

// ---------------------------------------------------------------------------
// heads: 1x1 convs (18 score + 36 loc = 54 outs) over 512 channels.
// Block: 256 threads, 16 pixels. thread: o = t&63 (54 used), ty = t>>6 (4 px).
// ---------------------------------------------------------------------------
__global__ __launch_bounds__(256) void k_heads(const float* __restrict__ sw,
                                               const float* __restrict__ sb,
                                               const float* __restrict__ lw,
                                               const float* __restrict__ lb,
                                               float* __restrict__ out) {
    const int n  = blockIdx.y;
    const int p0 = blockIdx.x * 16;
    __shared__ float fs[16][68];
    __shared__ float wsm[54][65];
    const int t  = threadIdx.x;
    const int o  = t & 63;
    const int ty = t >> 6;
    float acc[4] = {0.f, 0.f, 0.f, 0.f};

    for (int c0 = 0; c0 < C; c0 += 64) {
        for (int i = t; i < 16 * 64; i += 256) {
            int px = i >> 6, ic = i & 63;
            int p = p0 + px;
            fs[px][ic] = (p < HW) ? g_feat[((size_t)n * HW + p) * C + c0 + ic] : 0.f;
        }
        for (int i = t; i < 54 * 64; i += 256) {
            int oo = i >> 6, ic = i & 63;
            wsm[oo][ic] = (oo < 18) ? sw[oo * C + c0 + ic] : lw[(oo - 18) * C + c0 + ic];
        }
        __syncthreads();
        if (o < 54) {
#pragma unroll 16
            for (int ic = 0; ic < 64; ++ic) {
                float wv = wsm[o][ic];
#pragma unroll
                for (int pi = 0; pi < 4; ++pi) acc[pi] += wv * fs[ty * 4 + pi][ic];
            }
        }
        __syncthreads();
    }
    if (o < 54) {
        float bb = (o < 18) ? sb[o] : lb[o - 18];
#pragma unroll
        for (int pi = 0; pi < 4; ++pi) {
            int p = p0 + ty * 4 + pi;
            if (p < HW) {
                float v = acc[pi] + bb;
                if (o < 18) {
                    int a = o >> 1, cls = o & 1;
                    out[SCORE_OFF + ((size_t)n * NA + (size_t)p * 9 + a) * 2 + cls] = v;
                } else {
                    int c = o - 18, a = c >> 2, coord = c & 3;
                    out[LOC_OFF + ((size_t)n * NA + (size_t)p * 9 + a) * 4 + coord] = v;
                }
            }
        }
    }
}

// ---------------------------------------------------------------------------
// decode: anchors + loc2bbox + clip + valid + softmax-fg -> sortable keys
// ---------------------------------------------------------------------------
__global__ void k_decode(const float* __restrict__ out,
                         const int* __restrict__ ih, const int* __restrict__ iw,
                         float* __restrict__ outw) {
    int id = blockIdx.x * blockDim.x + threadIdx.x;
    if (id >= NB * SORTN) return;
    int n = id >> 16, site = id & (SORTN - 1);
    if (site >= NA) { g_keys[(size_t)n * SORTN + site] = 0ull; return; }

    int p = site / 9, a = site % 9;
    int yy = p / W, xx = p % W;
    int ri = a / 3, sj = a % 3;
    const float ratios[3] = {0.5f, 1.0f, 2.0f};
    const float scales[3] = {8.0f, 16.0f, 32.0f};
    float r = ratios[ri], s = scales[sj];
    float hh = 16.0f * s * sqrtf(r);
    float ww = 16.0f * s * sqrtf(1.0f / r);
    float sx = (float)xx * 16.0f, sy = (float)yy * 16.0f;
    float a0 = sx + (8.0f - ww * 0.5f);
    float a1 = sy + (8.0f - hh * 0.5f);
    float a2 = sx + (8.0f + ww * 0.5f);
    float a3 = sy + (8.0f + hh * 0.5f);
    if (n == 0) {
        float* ao = outw + ANCH_OFF + (size_t)site * 4;
        ao[0] = a0; ao[1] = a1; ao[2] = a2; ao[3] = a3;
    }
    const float* lp = out + LOC_OFF + ((size_t)n * NA + site) * 4;
    float l0 = lp[0], l1 = lp[1], l2 = lp[2], l3 = lp[3];
    float aw = a2 - a0, ah = a3 - a1;
    float ax = a0 + 0.5f * aw, ay = a1 + 0.5f * ah;
    float cx = l0 * aw + ax, cy = l1 * ah + ay;
    float bw = (float)exp((double)l2) * aw;
    float bh = (float)exp((double)l3) * ah;
    float Wf = (float)(*iw), Hf = (float)(*ih);
    float x1 = fminf(fmaxf(cx - 0.5f * bw, 0.f), Wf);
    float y1 = fminf(fmaxf(cy - 0.5f * bh, 0.f), Hf);
    float x2 = fminf(fmaxf(cx + 0.5f * bw, 0.f), Wf);
    float y2 = fminf(fmaxf(cy + 0.5f * bh, 0.f), Hf);
    float* bo = g_boxes + ((size_t)n * NA + site) * 4;
    bo[0] = x1; bo[1] = y1; bo[2] = x2; bo[3] = y2;
    bool valid = ((x2 - x1) >= 16.0f) && ((y2 - y1) >= 16.0f);
    const float* sp = out + SCORE_OFF + ((size_t)n * NA + site) * 2;
    float s0 = sp[0], s1 = sp[1];
    float m = fmaxf(s0, s1);
    float e0 = (float)exp((double)(s0 - m));
    float e1 = (float)exp((double)(s1 - m));
    float fg = e1 / (e0 + e1);
    float sc = valid ? fg : -INFINITY;
    unsigned ub = __float_as_uint(sc);
    unsigned u  = (ub & 0x80000000u) ? ~ub : (ub | 0x80000000u);
    g_keys[(size_t)n * SORTN + site] =
        ((unsigned long long)u << 32) | (unsigned)(~(unsigned)site);
}

// ---------------------------------------------------------------------------
// Bitonic sort, descending, 65536 keys per image.
// ---------------------------------------------------------------------------
__global__ __launch_bounds__(1024) void k_sort_local() {
    __shared__ unsigned long long sm[2048];
    const int n = blockIdx.y, ch = blockIdx.x;
    unsigned long long* base = g_keys + (size_t)n * SORTN + (size_t)ch * 2048;
    const int t = threadIdx.x;
    sm[t] = base[t]; sm[t + 1024] = base[t + 1024];
    __syncthreads();
    const int gbase = ch * 2048;
    for (int k = 2; k <= 2048; k <<= 1) {
        for (int j = k >> 1; j > 0; j >>= 1) {
            int i = ((t & ~(j - 1)) << 1) | (t & (j - 1));
            int p = i | j;
            bool descBlk = (((gbase + i) & k) == 0);
            unsigned long long A = sm[i], B = sm[p];
            bool sw = descBlk ? (A < B) : (A > B);
            if (sw) { sm[i] = B; sm[p] = A; }
            __syncthreads();
        }
    }
    base[t] = sm[t]; base[t + 1024] = sm[t + 1024];
}

__global__ void k_sort_global(int k, int j) {
    int t = blockIdx.x * blockDim.x + threadIdx.x;   // 0..32767
    int n = blockIdx.y;
    int i = ((t & ~(j - 1)) << 1) | (t & (j - 1));
    int p = i | j;
    unsigned long long* base = g_keys + (size_t)n * SORTN;
    unsigned long long A = base[i], B = base[p];
    bool descBlk = ((i & k) == 0);
    bool sw = descBlk ? (A < B) : (A > B);
    if (sw) { base[i] = B; base[p] = A; }
}

__global__ __launch_bounds__(1024) void k_sort_localmerge(int k) {
    __shared__ unsigned long long sm[2048];
    const int n = blockIdx.y, ch = blockIdx.x;
    unsigned long long* base = g_keys + (size_t)n * SORTN + (size_t)ch * 2048;
    const int t = threadIdx.x;
    sm[t] = base[t]; sm[t + 1024] = base[t + 1024];
    __syncthreads();
    const bool descBlk = (((ch * 2048) & k) == 0);
    for (int j = 1024; j > 0; j >>= 1) {
        int i = ((t & ~(j - 1)) << 1) | (t & (j - 1));
        int p = i | j;
        unsigned long long A = sm[i], B = sm[p];
        bool sw = descBlk ? (A < B) : (A > B);
        if (sw) { sm[i] = B; sm[p] = A; }
        __syncthreads();
    }
    base[t] = sm[t]; base[t + 1024] = sm[t + 1024];
}

// ---------------------------------------------------------------------------
// gather top-6000 boxes/areas/finite flags in sorted order
// ---------------------------------------------------------------------------
__global__ void k_gather() {
    int id = blockIdx.x * blockDim.x + threadIdx.x;
    if (id >= NB * PRE) return;
    int n = id / PRE, r = id % PRE;
    unsigned long long key = g_keys[(size_t)n * SORTN + r];
    unsigned site = ~(unsigned)key;
    bool fin = ((unsigned)(key >> 32)) > 0x007FFFFFu;
    float b0 = 0.f, b1 = 0.f, b2 = 0.f, b3 = 0.f;
    if (site < NA) {
        const float* bx = g_boxes + ((size_t)n * NA + site) * 4;
        b0 = bx[0]; b1 = bx[1]; b2 = bx[2]; b3 = bx[3];
    }
    float* sb = g_sbox + ((size_t)n * PRE + r) * 4;
    sb[0] = b0; sb[1] = b1; sb[2] = b2; sb[3] = b3;
    g_sarea[(size_t)n * PRE + r] = (b2 - b0) * (b3 - b1);
    g_sfin[(size_t)n * PRE + r]  = fin ? 1 : 0;
}

// ---------------------------------------------------------------------------
// mask: bit (i, j) set iff j>i and IoU(i,j) > 0.7
// ---------------------------------------------------------------------------
__global__ void k_mask() {
    int id = blockIdx.x * blockDim.x + threadIdx.x;
    int n = blockIdx.y;
    if (id >= PRE * WORDS) return;
    int i = id / WORDS, w_ = id % WORDS;
    unsigned long long bits = 0ull;
    if (w_ * 64 + 63 > i) {
        const float* bi = g_sbox + ((size_t)n * PRE + i) * 4;
        float ix1 = bi[0], iy1 = bi[1], ix2 = bi[2], iy2 = bi[3];
        float ia = g_sarea[(size_t)n * PRE + i];
        int jmax = min(64, PRE - w_ * 64);
        for (int jj = 0; jj < jmax; ++jj) {
            int j = w_ * 64 + jj;
            if (j <= i) continue;
            const float* bj = g_sbox + ((size_t)n * PRE + j) * 4;
            float xx1 = fmaxf(ix1, bj[0]);
            float yy1 = fmaxf(iy1, bj[1]);
            float xx2 = fminf(ix2, bj[2]);
            float yy2 = fminf(iy2, bj[3]);
            float iw_ = fmaxf(xx2 - xx1, 0.f);
            float ihh = fmaxf(yy2 - yy1, 0.f);
            float inter = iw_ * ihh;
            float denom = ((ia + g_sarea[(size_t)n * PRE + j]) - inter) + 1e-9f;
            float iou = inter / denom;
            if (iou > 0.7f) bits |= (1ull << jj);
        }
    }
    g_mask[((size_t)n * PRE + i) * WORDS + w_] = bits;
}

// ---------------------------------------------------------------------------
// scan: greedy NMS (word-sequential), then emit first 300 kept boxes
// ---------------------------------------------------------------------------
__global__ __launch_bounds__(128) void k_scan(float* __restrict__ out) {
    const int n = blockIdx.x;
    __shared__ unsigned long long keep[WORDS];
    __shared__ unsigned long long mrow[64];
    __shared__ unsigned long long remv;
    const int t = threadIdx.x;
    if (t < WORDS) {
        unsigned long long wbits = 0ull;
        for (int b = 0; b < 64; ++b) {
            int i = t * 64 + b;
            if (i < PRE && g_sfin[(size_t)n * PRE + i]) wbits |= (1ull << b);
        }
        keep[t] = wbits;
    }
    __syncthreads();
    for (int w_ = 0; w_ < WORDS; ++w_) {
        if (t == 0) remv = 0ull;
        if (t < 64) {
            int i = w_ * 64 + t;
            mrow[t] = (i < PRE) ? g_mask[((size_t)n * PRE + i) * WORDS + w_] : 0ull;
        }
        __syncthreads();
        unsigned long long loc = 0ull;
        for (int i = t; i < w_ * 64; i += 128)
            if ((keep[i >> 6] >> (i & 63)) & 1ull)
                loc |= g_mask[((size_t)n * PRE + i) * WORDS + w_];
        if (loc) atomicOr(&remv, loc);
        __syncthreads();
        if (t == 0) {
            unsigned long long kw = keep[w_] & ~remv;
            unsigned long long res = 0ull;
            for (int b = 0; b < 64; ++b) {
                if ((kw >> b) & 1ull) { res |= (1ull << b); kw &= ~mrow[b]; }
            }
            keep[w_] = res;
        }
        __syncthreads();
    }
    if (t == 0) {
        int r = 0;
        for (int i = 0; i < PRE && r < POST; ++i) {
            if ((keep[i >> 6] >> (i & 63)) & 1ull) {
                float* o = out + ROI_OFF + ((size_t)n * POST + r) * 4;
                const float* bx = g_sbox + ((size_t)n * PRE + i) * 4;
                o[0] = bx[0]; o[1] = bx[1]; o[2] = bx[2]; o[3] = bx[3];
                ++r;
            }
        }
        for (; r < POST; ++r) {
            float* o = out + ROI_OFF + ((size_t)n * POST + r) * 4;
            o[0] = 0.f; o[1] = 0.f; o[2] = 0.f; o[3] = 0.f;
        }
    }
}

// ---------------------------------------------------------------------------
extern "C" void kernel_launch(void* const* d_in, const int* in_sizes, int n_in,
                              void* d_out, int out_size) {
    const float* x       = (const float*)d_in[0];
    const float* conv1_w = (const float*)d_in[1];
    const float* conv1_b = (const float*)d_in[2];
    const float* score_w = (const float*)d_in[3];
    const float* score_b = (const float*)d_in[4];
    const float* loc_w   = (const float*)d_in[5];
    const float* loc_b   = (const float*)d_in[6];
    const int*   img_h   = (const int*)d_in[7];
    const int*   img_w   = (const int*)d_in[8];
    float* out = (float*)d_out;

    k_wt<<<(C * C * 9 + 255) / 256, 256>>>(conv1_w);
    k_conv1<<<dim3(8, 25, NB), 128>>>(x, conv1_b);
    k_heads<<<dim3((HW + 15) / 16, NB), 256>>>(score_w, score_b, loc_w, loc_b, out);
    k_decode<<<(NB * SORTN + 255) / 256, 256>>>(out, img_h, img_w, out);

    k_sort_local<<<dim3(SORTN / 2048, NB), 1024>>>();
    for (int k = 4096; k <= SORTN; k <<= 1) {
        for (int j = k >> 1; j >= 2048; j >>= 1)
            k_sort_global<<<dim3(SORTN / 2 / 256, NB), 256>>>(k, j);
        k_sort_localmerge<<<dim3(SORTN / 2048, NB), 1024>>>(k);
    }

    k_gather<<<(NB * PRE + 255) / 256, 256>>>();
    k_mask<<<dim3((PRE * WORDS + 255) / 256, NB), 256>>>();
    k_scan<<<NB, 128>>>(out);
}